// round 2
// baseline (speedup 1.0000x reference)
#include <cuda_runtime.h>
#include <cuda_bf16.h>
#include <cstdint>

// Embedding_78666620994160
// out[t, e] = (W[e, ids[t]] + b[e]) * sqrt(512)
// ids: [8*4096] int32, W: [512, 50257] f32 (row-major), b: [512] f32
// out: [8*4096, 512] f32
//
// Strategy: counting-sort tokens by id so gather accesses to the same W
// sectors are temporally adjacent -> L2 captures all reuse, DRAM reads
// drop from ~590MB to ~103MB (each sector once).

#define VOCAB 50257
#define EMB   512
#define N_TOKENS (8 * 4096)

__device__ int g_hist[VOCAB];      // histogram
__device__ int g_offs[VOCAB];      // exclusive prefix (consumed by scatter)
__device__ int g_sorted[N_TOKENS]; // token indices in id-sorted order

// ---------------- sort pipeline ----------------

__global__ void zero_hist_kernel()
{
    int i = blockIdx.x * blockDim.x + threadIdx.x;
    if (i < VOCAB) g_hist[i] = 0;
}

__global__ void hist_kernel(const int* __restrict__ ids)
{
    int t = blockIdx.x * blockDim.x + threadIdx.x;
    if (t < N_TOKENS) atomicAdd(&g_hist[__ldg(&ids[t])], 1);
}

// Single-block exclusive scan over VOCAB bins (1024 threads, chunked).
__global__ void scan_kernel()
{
    __shared__ int sm[1024];
    __shared__ int carry_s;
    int tid = threadIdx.x;
    if (tid == 0) carry_s = 0;
    __syncthreads();

    for (int base = 0; base < VOCAB; base += 1024) {
        int i = base + tid;
        int v = (i < VOCAB) ? g_hist[i] : 0;
        sm[tid] = v;
        __syncthreads();
        // Hillis-Steele inclusive scan
        #pragma unroll
        for (int off = 1; off < 1024; off <<= 1) {
            int t = (tid >= off) ? sm[tid - off] : 0;
            __syncthreads();
            sm[tid] += t;
            __syncthreads();
        }
        int incl = sm[tid];
        int excl = incl - v;
        if (i < VOCAB) g_offs[i] = excl + carry_s;
        __syncthreads();
        if (tid == 1023) carry_s += incl;  // total of this chunk
        __syncthreads();
    }
}

__global__ void scatter_kernel(const int* __restrict__ ids)
{
    int t = blockIdx.x * blockDim.x + threadIdx.x;
    if (t < N_TOKENS) {
        int id  = __ldg(&ids[t]);
        int pos = atomicAdd(&g_offs[id], 1);
        g_sorted[pos] = t;
    }
}

// ---------------- gather (id-sorted order) ----------------

__global__ void __launch_bounds__(512, 4)
emb_gather_sorted_kernel(const int* __restrict__ ids,
                         const float* __restrict__ W,
                         const float* __restrict__ b,
                         float* __restrict__ out)
{
    const float SCALE = 22.62741699796952f; // sqrt(512)

    // blockDim = (128, 4): x covers EMB/4 float4 lanes, y covers 4 tokens
    int s = blockIdx.x * 4 + threadIdx.y;   // position in sorted order
    int token = __ldg(&g_sorted[s]);
    int id    = __ldg(&ids[token]);

    int e4 = threadIdx.x;                    // 0..127 (float4 lane along EMB)
    float4 bv = __ldg(((const float4*)b) + e4);

    // Column gather: 4 independent strided loads. Sorted order means the
    // live id-window across the chip is small -> sectors stay in L2.
    const float* wp = W + (size_t)(e4 * 4) * VOCAB + id;
    float x0 = __ldg(wp);
    float x1 = __ldg(wp + (size_t)VOCAB);
    float x2 = __ldg(wp + (size_t)2 * VOCAB);
    float x3 = __ldg(wp + (size_t)3 * VOCAB);

    float4 r;
    r.x = (x0 + bv.x) * SCALE;
    r.y = (x1 + bv.y) * SCALE;
    r.z = (x2 + bv.z) * SCALE;
    r.w = (x3 + bv.w) * SCALE;

    // Fully coalesced 16B store into this token's own row
    ((float4*)out)[(size_t)token * (EMB / 4) + e4] = r;
}

extern "C" void kernel_launch(void* const* d_in, const int* in_sizes, int n_in,
                              void* d_out, int out_size)
{
    const int*   ids = (const int*)d_in[0];    // [32768] int32
    const float* W   = (const float*)d_in[1];  // [512*50257]
    const float* b   = (const float*)d_in[2];  // [512]
    float*       out = (float*)d_out;          // [32768*512]

    zero_hist_kernel<<<(VOCAB + 255) / 256, 256>>>();
    hist_kernel<<<(N_TOKENS + 255) / 256, 256>>>(ids);
    scan_kernel<<<1, 1024>>>();
    scatter_kernel<<<(N_TOKENS + 255) / 256, 256>>>(ids);

    dim3 block(128, 4, 1);
    dim3 grid(N_TOKENS / 4, 1, 1);
    emb_gather_sorted_kernel<<<grid, block>>>(ids, W, b, out);
}

// round 3
// speedup vs baseline: 1.7567x; 1.7567x over previous
#include <cuda_runtime.h>
#include <cuda_bf16.h>
#include <cstdint>

// Embedding_78666620994160
// out[t, e] = (W[e, ids[t]] + b[e]) * sqrt(512)
// ids: [8*4096] int32, W: [512, 50257] f32 (row-major), b: [512] f32
// out: [8*4096, 512] f32
//
// Strategy: bucket tokens by id>>5 (sector-granularity approximate sort)
// so gather accesses to the same W 32B sectors are temporally adjacent.
// L2 then captures all sector reuse: DRAM reads drop ~590MB -> ~103MB.

#define VOCAB    50257
#define EMB      512
#define N_TOKENS (8 * 4096)
#define BUCKET_SHIFT 5
#define NBUCKETS ((VOCAB >> BUCKET_SHIFT) + 1)   // 1571
#define NBINS_PAD 2048

__device__ int  g_offs[NBINS_PAD];     // exclusive prefix (consumed by scatter)
__device__ int2 g_sorted[N_TOKENS];    // (token, id) in bucket-sorted order

// ---- fused zero + histogram + scan (single block, 1024 threads) ----
__global__ void __launch_bounds__(1024, 1)
hist_scan_kernel(const int* __restrict__ ids)
{
    __shared__ int h[NBINS_PAD];
    __shared__ int sm[1024];
    __shared__ int carry_s;
    int tid = threadIdx.x;

    h[tid] = 0;
    h[tid + 1024] = 0;
    if (tid == 0) carry_s = 0;
    __syncthreads();

    // histogram into smem bins
    for (int t = tid; t < N_TOKENS; t += 1024)
        atomicAdd(&h[__ldg(&ids[t]) >> BUCKET_SHIFT], 1);
    __syncthreads();

    // exclusive scan over 2048 bins: 2 chunks of 1024 (Hillis-Steele)
    #pragma unroll
    for (int chunk = 0; chunk < 2; chunk++) {
        int i = chunk * 1024 + tid;
        int v = h[i];
        sm[tid] = v;
        __syncthreads();
        #pragma unroll
        for (int off = 1; off < 1024; off <<= 1) {
            int t = (tid >= off) ? sm[tid - off] : 0;
            __syncthreads();
            sm[tid] += t;
            __syncthreads();
        }
        int incl = sm[tid];
        g_offs[i] = incl - v + carry_s;
        __syncthreads();
        if (tid == 1023) carry_s += incl;
        __syncthreads();
    }
}

// ---- scatter tokens into bucket-sorted order ----
__global__ void scatter_kernel(const int* __restrict__ ids)
{
    int t = blockIdx.x * blockDim.x + threadIdx.x;
    if (t < N_TOKENS) {
        int id  = __ldg(&ids[t]);
        int pos = atomicAdd(&g_offs[id >> BUCKET_SHIFT], 1);
        g_sorted[pos] = make_int2(t, id);
    }
}

// ---- gather in bucket-sorted order ----
__global__ void __launch_bounds__(512, 4)
emb_gather_sorted_kernel(const float* __restrict__ W,
                         const float* __restrict__ b,
                         float* __restrict__ out)
{
    const float SCALE = 22.62741699796952f; // sqrt(512)

    // blockDim = (128, 4): x covers EMB/4 float4 lanes, y covers 4 tokens
    int s = blockIdx.x * 4 + threadIdx.y;   // position in sorted order
    int2 ti   = __ldg(&g_sorted[s]);
    int token = ti.x;
    int id    = ti.y;

    int e4 = threadIdx.x;                    // 0..127 (float4 lane along EMB)
    float4 bv = __ldg(((const float4*)b) + e4);

    // Column gather: 4 independent strided loads. Bucket-sorted order keeps
    // the chip-wide live id-window small -> sectors stay resident in L2.
    const float* wp = W + (size_t)(e4 * 4) * VOCAB + id;
    float x0 = __ldg(wp);
    float x1 = __ldg(wp + (size_t)VOCAB);
    float x2 = __ldg(wp + (size_t)2 * VOCAB);
    float x3 = __ldg(wp + (size_t)3 * VOCAB);

    float4 r;
    r.x = (x0 + bv.x) * SCALE;
    r.y = (x1 + bv.y) * SCALE;
    r.z = (x2 + bv.z) * SCALE;
    r.w = (x3 + bv.w) * SCALE;

    // Fully coalesced 16B store into this token's own row
    ((float4*)out)[(size_t)token * (EMB / 4) + e4] = r;
}

extern "C" void kernel_launch(void* const* d_in, const int* in_sizes, int n_in,
                              void* d_out, int out_size)
{
    const int*   ids = (const int*)d_in[0];    // [32768] int32
    const float* W   = (const float*)d_in[1];  // [512*50257]
    const float* b   = (const float*)d_in[2];  // [512]
    float*       out = (float*)d_out;          // [32768*512]

    hist_scan_kernel<<<1, 1024>>>(ids);
    scatter_kernel<<<(N_TOKENS + 255) / 256, 256>>>(ids);

    dim3 block(128, 4, 1);
    dim3 grid(N_TOKENS / 4, 1, 1);
    emb_gather_sorted_kernel<<<grid, block>>>(W, b, out);
}

// round 4
// speedup vs baseline: 2.5822x; 1.4699x over previous
#include <cuda_runtime.h>
#include <cuda_bf16.h>
#include <cstdint>

// Embedding_78666620994160
// out[t, e] = (W[e, ids[t]] + b[e]) * sqrt(512)
// ids: [8*4096] int32, W: [512, 50257] f32 (row-major), b: [512] f32
// out: [8*4096, 512] f32
//
// v3: bucket-sort (id>>5) for L2 locality + transposed gather:
//   lanes = sorted tokens -> warp gather addresses fall in few 32B sectors
//   (coalesced), tile staged in smem, output written token-major float4.
// Read sector traffic ~537MB -> ~130MB; gather becomes DRAM-bound.

#define VOCAB    50257
#define EMB      512
#define N_TOKENS (8 * 4096)
#define BUCKET_SHIFT 5
#define NBINS_PAD 2048

__device__ int  g_hist[NBINS_PAD];
__device__ int  g_offs[NBINS_PAD];     // exclusive prefix (consumed by scatter)
__device__ int2 g_sorted[N_TOKENS];    // (token, id) in bucket-sorted order

// ---------------- sort pipeline ----------------

__global__ void zero_kernel()
{
    g_hist[blockIdx.x * 256 + threadIdx.x] = 0;
}

__global__ void hist_kernel(const int4* __restrict__ ids4)
{
    int i = blockIdx.x * blockDim.x + threadIdx.x;   // 8192 threads
    int4 v = __ldg(&ids4[i]);
    atomicAdd(&g_hist[v.x >> BUCKET_SHIFT], 1);
    atomicAdd(&g_hist[v.y >> BUCKET_SHIFT], 1);
    atomicAdd(&g_hist[v.z >> BUCKET_SHIFT], 1);
    atomicAdd(&g_hist[v.w >> BUCKET_SHIFT], 1);
}

// exclusive scan over 2048 bins (1 block, 1024 threads, 2 chunks)
__global__ void __launch_bounds__(1024, 1)
scan_kernel()
{
    __shared__ int sm[1024];
    __shared__ int carry_s;
    int tid = threadIdx.x;
    if (tid == 0) carry_s = 0;
    __syncthreads();

    #pragma unroll
    for (int chunk = 0; chunk < 2; chunk++) {
        int i = chunk * 1024 + tid;
        int v = g_hist[i];
        sm[tid] = v;
        __syncthreads();
        #pragma unroll
        for (int off = 1; off < 1024; off <<= 1) {
            int t = (tid >= off) ? sm[tid - off] : 0;
            __syncthreads();
            sm[tid] += t;
            __syncthreads();
        }
        int incl = sm[tid];
        g_offs[i] = incl - v + carry_s;
        __syncthreads();
        if (tid == 1023) carry_s += incl;
        __syncthreads();
    }
}

__global__ void scatter_kernel(const int4* __restrict__ ids4)
{
    int i = blockIdx.x * blockDim.x + threadIdx.x;   // 8192 threads
    int4 v = __ldg(&ids4[i]);
    int t0 = i * 4;
    int p;
    p = atomicAdd(&g_offs[v.x >> BUCKET_SHIFT], 1); g_sorted[p] = make_int2(t0 + 0, v.x);
    p = atomicAdd(&g_offs[v.y >> BUCKET_SHIFT], 1); g_sorted[p] = make_int2(t0 + 1, v.y);
    p = atomicAdd(&g_offs[v.z >> BUCKET_SHIFT], 1); g_sorted[p] = make_int2(t0 + 2, v.z);
    p = atomicAdd(&g_offs[v.w >> BUCKET_SHIFT], 1); g_sorted[p] = make_int2(t0 + 3, v.w);
}

// ---------------- transposed gather ----------------
// Block tile: 32 sorted tokens x 64 float4 (=256 dims). blockIdx.y picks
// which half of EMB. blockDim = (32, 16) = 512 threads.
// Phase 1: lane = token -> warp gather hits few sectors (sorted ids).
// Phase 2: coalesced float4 stores, token-major.
// Smem pitch 65 float4 per token row: 65 = 1 mod 8 -> STS.128/LDS.128
// quarter-warps hit distinct 16B bank groups in both phases.

#define TOK_PER_BLK 32
#define E4_PER_BLK  64
#define S4_PITCH    65

__global__ void __launch_bounds__(512, 4)
emb_gather_tr_kernel(const float* __restrict__ W,
                     const float* __restrict__ b,
                     float* __restrict__ out)
{
    const float SCALE = 22.62741699796952f; // sqrt(512)
    __shared__ float4 S4[TOK_PER_BLK * S4_PITCH];

    int t  = threadIdx.x;                        // 0..31 local token
    int ty = threadIdx.y;                        // 0..15
    int s  = blockIdx.x * TOK_PER_BLK + t;       // sorted position
    int e4base = blockIdx.y * E4_PER_BLK;        // global float4 offset

    int id = __ldg(&g_sorted[s]).y;

    // Phase 1: gather 4 e4-slots per thread
    #pragma unroll
    for (int i = 0; i < 4; i++) {
        int e4l = ty + 16 * i;                   // 0..63 local
        int e4g = e4base + e4l;
        float4 bv = __ldg((const float4*)b + e4g);
        const float* wp = W + (size_t)(4 * e4g) * VOCAB + id;
        float4 r;
        r.x = (__ldg(wp)                      + bv.x) * SCALE;
        r.y = (__ldg(wp + (size_t)VOCAB)      + bv.y) * SCALE;
        r.z = (__ldg(wp + (size_t)2 * VOCAB)  + bv.z) * SCALE;
        r.w = (__ldg(wp + (size_t)3 * VOCAB)  + bv.w) * SCALE;
        S4[t * S4_PITCH + e4l] = r;
    }

    __syncthreads();

    // Phase 2: token-major coalesced float4 stores
    int tid  = ty * 32 + t;                      // 0..511
    int tl   = tid >> 4;                         // 0..31 local token
    int ey   = tid & 15;                         // 0..15
    int token = __ldg(&g_sorted[blockIdx.x * TOK_PER_BLK + tl]).x;
    float4* outp = (float4*)out + (size_t)token * (EMB / 4) + e4base;
    #pragma unroll
    for (int i = 0; i < 4; i++) {
        int e4l = ey + 16 * i;
        outp[e4l] = S4[tl * S4_PITCH + e4l];
    }
}

extern "C" void kernel_launch(void* const* d_in, const int* in_sizes, int n_in,
                              void* d_out, int out_size)
{
    const int*   ids = (const int*)d_in[0];    // [32768] int32
    const float* W   = (const float*)d_in[1];  // [512*50257]
    const float* b   = (const float*)d_in[2];  // [512]
    float*       out = (float*)d_out;          // [32768*512]
    const int4*  ids4 = (const int4*)ids;

    zero_kernel<<<NBINS_PAD / 256, 256>>>();
    hist_kernel<<<(N_TOKENS / 4) / 256, 256>>>(ids4);
    scan_kernel<<<1, 1024>>>();
    scatter_kernel<<<(N_TOKENS / 4) / 256, 256>>>(ids4);

    dim3 block(32, 16, 1);
    dim3 grid(N_TOKENS / TOK_PER_BLK, EMB / (4 * E4_PER_BLK), 1);  // 1024 x 2
    emb_gather_tr_kernel<<<grid, block>>>(W, b, out);
}

// round 5
// speedup vs baseline: 2.8700x; 1.1114x over previous
#include <cuda_runtime.h>
#include <cuda_bf16.h>
#include <cstdint>

// Embedding_78666620994160
// out[t, e] = (W[e, ids[t]] + b[e]) * sqrt(512)
// ids: [8*4096] int32, W: [512, 50257] f32 (row-major), b: [512] f32
// out: [8*4096, 512] f32
//
// v4: bucket-sort (id>>5) for L2 locality + transposed smem gather.
// Prelude slimmed: scan clears hist (no zero kernel), 1 token/thread
// hist+scatter (parallel atomics), shfl-based scan.

#define VOCAB    50257
#define EMB      512
#define N_TOKENS (8 * 4096)
#define BUCKET_SHIFT 5
#define NBINS_PAD 2048

__device__ int  g_hist[NBINS_PAD];     // zero at load; scan re-zeroes each launch
__device__ int  g_offs[NBINS_PAD];     // exclusive prefix (consumed by scatter)
__device__ int2 g_sorted[N_TOKENS];    // (token, id) in bucket-sorted order

// ---------------- sort pipeline ----------------

__global__ void hist_kernel(const int* __restrict__ ids)
{
    int t = blockIdx.x * blockDim.x + threadIdx.x;   // 32768 threads
    atomicAdd(&g_hist[__ldg(&ids[t]) >> BUCKET_SHIFT], 1);
}

// Exclusive scan over 2048 bins, 1 block x 1024 threads, 2 bins/thread.
// Also clears g_hist for the next graph replay.
__global__ void __launch_bounds__(1024, 1)
scan_kernel()
{
    __shared__ int warpsum[32];
    int tid  = threadIdx.x;
    int lane = tid & 31;
    int wid  = tid >> 5;

    int a = g_hist[2 * tid];
    int c = g_hist[2 * tid + 1];
    g_hist[2 * tid]     = 0;
    g_hist[2 * tid + 1] = 0;
    int s = a + c;

    // warp inclusive scan of s
    int x = s;
    #pragma unroll
    for (int off = 1; off < 32; off <<= 1) {
        int y = __shfl_up_sync(0xffffffffu, x, off);
        if (lane >= off) x += y;
    }
    if (lane == 31) warpsum[wid] = x;
    __syncthreads();

    if (wid == 0) {
        int w = warpsum[lane];
        int xw = w;
        #pragma unroll
        for (int off = 1; off < 32; off <<= 1) {
            int y = __shfl_up_sync(0xffffffffu, xw, off);
            if (lane >= off) xw += y;
        }
        warpsum[lane] = xw - w;   // exclusive warp base
    }
    __syncthreads();

    int base = warpsum[wid] + (x - s);   // exclusive prefix for this thread's pair
    g_offs[2 * tid]     = base;
    g_offs[2 * tid + 1] = base + a;
}

__global__ void scatter_kernel(const int* __restrict__ ids)
{
    int t = blockIdx.x * blockDim.x + threadIdx.x;   // 32768 threads
    int id  = __ldg(&ids[t]);
    int pos = atomicAdd(&g_offs[id >> BUCKET_SHIFT], 1);
    __stcs(&g_sorted[pos], make_int2(t, id));
}

// ---------------- transposed gather ----------------
// Block tile: 32 sorted tokens x 64 float4 (=256 dims). blockIdx.y picks
// which half of EMB. blockDim = (32, 16) = 512 threads.
// Phase 1: lane = token -> warp gather hits few 32B sectors (sorted ids).
// Phase 2: coalesced float4 streaming stores, token-major.
// Smem pitch 65 float4/row avoids bank conflicts in both phases.

#define TOK_PER_BLK 32
#define E4_PER_BLK  64
#define S4_PITCH    65

__global__ void __launch_bounds__(512, 4)
emb_gather_tr_kernel(const float* __restrict__ W,
                     const float* __restrict__ b,
                     float* __restrict__ out)
{
    const float SCALE = 22.62741699796952f; // sqrt(512)
    __shared__ float4 S4[TOK_PER_BLK * S4_PITCH];

    int t  = threadIdx.x;                        // 0..31 local token
    int ty = threadIdx.y;                        // 0..15
    int s  = blockIdx.x * TOK_PER_BLK + t;       // sorted position
    int e4base = blockIdx.y * E4_PER_BLK;        // global float4 offset

    int id = __ldg(&g_sorted[s]).y;

    // Phase 1: gather 4 e4-slots per thread
    #pragma unroll
    for (int i = 0; i < 4; i++) {
        int e4l = ty + 16 * i;                   // 0..63 local
        int e4g = e4base + e4l;
        float4 bv = __ldg((const float4*)b + e4g);
        const float* wp = W + (size_t)(4 * e4g) * VOCAB + id;
        float4 r;
        r.x = (__ldg(wp)                      + bv.x) * SCALE;
        r.y = (__ldg(wp + (size_t)VOCAB)      + bv.y) * SCALE;
        r.z = (__ldg(wp + (size_t)2 * VOCAB)  + bv.z) * SCALE;
        r.w = (__ldg(wp + (size_t)3 * VOCAB)  + bv.w) * SCALE;
        S4[t * S4_PITCH + e4l] = r;
    }

    __syncthreads();

    // Phase 2: token-major coalesced float4 streaming stores
    int tid  = ty * 32 + t;                      // 0..511
    int tl   = tid >> 4;                         // 0..31 local token
    int ey   = tid & 15;                         // 0..15
    int token = __ldg(&g_sorted[blockIdx.x * TOK_PER_BLK + tl]).x;
    float4* outp = (float4*)out + (size_t)token * (EMB / 4) + e4base;
    #pragma unroll
    for (int i = 0; i < 4; i++) {
        int e4l = ey + 16 * i;
        __stcs(&outp[e4l], S4[tl * S4_PITCH + e4l]);
    }
}

extern "C" void kernel_launch(void* const* d_in, const int* in_sizes, int n_in,
                              void* d_out, int out_size)
{
    const int*   ids = (const int*)d_in[0];    // [32768] int32
    const float* W   = (const float*)d_in[1];  // [512*50257]
    const float* b   = (const float*)d_in[2];  // [512]
    float*       out = (float*)d_out;          // [32768*512]

    hist_kernel<<<N_TOKENS / 256, 256>>>(ids);
    scan_kernel<<<1, 1024>>>();
    scatter_kernel<<<N_TOKENS / 256, 256>>>(ids);

    dim3 block(32, 16, 1);
    dim3 grid(N_TOKENS / TOK_PER_BLK, EMB / (4 * E4_PER_BLK), 1);  // 1024 x 2
    emb_gather_tr_kernel<<<grid, block>>>(W, b, out);
}